// round 8
// baseline (speedup 1.0000x reference)
#include <cuda_runtime.h>
#include <cuda_fp16.h>
#include <math.h>

#define N_NODES 50000
#define N_EDGES 800000
#define H       96
#define IN_DIM  256
#define F       288   // combined output: [ h(96) | g_d(96) | g_s(96) ]

// Scratch (device globals — no allocation in kernel_launch)
__device__ __half g_hs[(size_t)N_NODES * 2 * H];   // [h(96) | g_s(96)] per node
__device__ __half g_gd[(size_t)N_NODES * H];       // g_d per node
__device__ float  g_WcT[IN_DIM * F];               // combined weight, tf32-pre-rounded
__device__ float  g_bc[F];
__device__ float  g_zacc[2 * N_NODES];

__device__ __forceinline__ unsigned f2tf32(float f) {
    unsigned u;
    asm("cvt.rna.tf32.f32 %0, %1;" : "=r"(u) : "f"(f));
    return u;
}

// ---------------------------------------------------------------------------
// Kernel 1: build combined weight WcT[k][r] (tf32-rounded) and bias; zero zacc.
// ---------------------------------------------------------------------------
__global__ void prep_kernel(const float* __restrict__ W_in, const float* __restrict__ b_in,
                            const float* __restrict__ W_gate, const float* __restrict__ b_gate) {
    int r = blockIdx.x;      // 0..287
    int k = threadIdx.x;     // 0..255
    float v;
    if (r < H) {
        v = W_in[r * IN_DIM + k];
    } else if (r < 2 * H) {
        int i = r - H;
        float acc = 0.f;
        #pragma unroll 4
        for (int j = 0; j < H; ++j) acc = fmaf(W_gate[i * (2 * H) + j], W_in[j * IN_DIM + k], acc);
        v = acc;
    } else {
        int i = r - 2 * H;
        float acc = 0.f;
        #pragma unroll 4
        for (int j = 0; j < H; ++j) acc = fmaf(W_gate[i * (2 * H) + H + j], W_in[j * IN_DIM + k], acc);
        v = acc;
    }
    g_WcT[k * F + r] = __uint_as_float(f2tf32(v));

    if (k == 0) {
        float b;
        if (r < H) {
            b = b_in[r];
        } else if (r < 2 * H) {
            int i = r - H;
            float acc = 0.f;
            for (int j = 0; j < H; ++j) acc = fmaf(W_gate[i * (2 * H) + j], b_in[j], acc);
            b = acc;
        } else {
            int i = r - 2 * H;
            float acc = 0.f;
            for (int j = 0; j < H; ++j) acc = fmaf(W_gate[i * (2 * H) + H + j], b_in[j], acc);
            b = acc + b_gate[i];
        }
        g_bc[r] = b;
    }

    for (int idx = blockIdx.x * blockDim.x + threadIdx.x; idx < 2 * N_NODES;
         idx += gridDim.x * blockDim.x)
        g_zacc[idx] = 0.f;
}

// ---------------------------------------------------------------------------
// Kernel 2: feat = x @ WcT + bc via tf32 mma, cp.async double-buffered.
//   Epilogue -> fp16: g_hs = [h | g_s], g_gd = g_d.
// ---------------------------------------------------------------------------
#define BM 128
#define BN 96
#define BK 32
#define AS_LD 36
#define BS_LD 104
#define KTILES (IN_DIM / BK)   // 8

__device__ __forceinline__ unsigned smem_u32(const void* p) {
    return (unsigned)__cvta_generic_to_shared(p);
}
__device__ __forceinline__ void cp_async16(unsigned dst, const void* src, bool valid) {
    int sz = valid ? 16 : 0;
    asm volatile("cp.async.cg.shared.global [%0], [%1], 16, %2;\n"
                 :: "r"(dst), "l"(src), "r"(sz));
}

__global__ __launch_bounds__(256) void gemm_tc_kernel(const float* __restrict__ x) {
    __shared__ float As[2][BM][AS_LD];
    __shared__ float Bs[2][BK][BS_LD];

    const int tid  = threadIdx.x;
    const int warp = tid >> 5;
    const int lane = tid & 31;
    const int gid  = lane >> 2;
    const int tig  = lane & 3;

    const int row0 = blockIdx.x * BM;
    const int col0 = blockIdx.y * BN;
    const int wm = warp >> 1;
    const int wn = warp & 1;
    const int m_warp = wm * 32;
    const int n_warp = wn * 48;

    float c[2][6][4];
    #pragma unroll
    for (int i = 0; i < 2; ++i)
        #pragma unroll
        for (int j = 0; j < 6; ++j)
            #pragma unroll
            for (int q = 0; q < 4; ++q) c[i][j][q] = 0.f;

    const int ar = tid >> 3;
    const int ac = (tid & 7) * 4;
    const int bk = tid >> 3;
    const int bc = (tid & 7) * 12;

    auto issue_tile = [&](int buf, int t) {
        int k0 = t * BK;
        #pragma unroll
        for (int p = 0; p < 4; ++p) {
            int r = ar + p * 32;
            int grow = row0 + r;
            bool valid = (grow < N_NODES);
            const float* srcp = x + (size_t)(valid ? grow : 0) * IN_DIM + k0 + ac;
            cp_async16(smem_u32(&As[buf][r][ac]), srcp, valid);
        }
        const float* bp = g_WcT + (size_t)(k0 + bk) * F + col0 + bc;
        #pragma unroll
        for (int q = 0; q < 3; ++q)
            cp_async16(smem_u32(&Bs[buf][bk][bc + q * 4]), bp + q * 4, true);
        asm volatile("cp.async.commit_group;\n");
    };

    issue_tile(0, 0);

    for (int t = 0; t < KTILES; ++t) {
        int cur = t & 1;
        if (t + 1 < KTILES) {
            issue_tile(cur ^ 1, t + 1);
            asm volatile("cp.async.wait_group 1;\n");
        } else {
            asm volatile("cp.async.wait_group 0;\n");
        }
        __syncthreads();

        #pragma unroll
        for (int ks = 0; ks < 4; ++ks) {
            const int kk = ks * 8;
            unsigned a[2][4], b[6][2];
            #pragma unroll
            for (int mt = 0; mt < 2; ++mt) {
                int rA = m_warp + mt * 16 + gid;
                a[mt][0] = f2tf32(As[cur][rA    ][kk + tig    ]);
                a[mt][1] = f2tf32(As[cur][rA + 8][kk + tig    ]);
                a[mt][2] = f2tf32(As[cur][rA    ][kk + tig + 4]);
                a[mt][3] = f2tf32(As[cur][rA + 8][kk + tig + 4]);
            }
            #pragma unroll
            for (int nt = 0; nt < 6; ++nt) {
                int cB = n_warp + nt * 8 + gid;
                b[nt][0] = __float_as_uint(Bs[cur][kk + tig    ][cB]);
                b[nt][1] = __float_as_uint(Bs[cur][kk + tig + 4][cB]);
            }
            #pragma unroll
            for (int mt = 0; mt < 2; ++mt)
                #pragma unroll
                for (int nt = 0; nt < 6; ++nt) {
                    asm volatile(
                        "mma.sync.aligned.m16n8k8.row.col.f32.tf32.tf32.f32 "
                        "{%0,%1,%2,%3}, {%4,%5,%6,%7}, {%8,%9}, {%0,%1,%2,%3};\n"
                        : "+f"(c[mt][nt][0]), "+f"(c[mt][nt][1]),
                          "+f"(c[mt][nt][2]), "+f"(c[mt][nt][3])
                        : "r"(a[mt][0]), "r"(a[mt][1]), "r"(a[mt][2]), "r"(a[mt][3]),
                          "r"(b[nt][0]), "r"(b[nt][1]));
                }
        }
        __syncthreads();
    }

    // epilogue: add bias, convert fp16, scatter into g_hs / g_gd.
    #pragma unroll
    for (int mt = 0; mt < 2; ++mt) {
        #pragma unroll
        for (int hf = 0; hf < 2; ++hf) {
            int grow = row0 + m_warp + mt * 16 + gid + hf * 8;
            if (grow >= N_NODES) continue;
            #pragma unroll
            for (int nt = 0; nt < 6; ++nt) {
                int gc = col0 + n_warp + nt * 8 + 2 * tig;
                float v0 = c[mt][nt][hf * 2 + 0] + g_bc[gc];
                float v1 = c[mt][nt][hf * 2 + 1] + g_bc[gc + 1];
                __half2 hv = __floats2half2_rn(v0, v1);
                if (gc < H)
                    *reinterpret_cast<__half2*>(&g_hs[(size_t)grow * 2 * H + gc]) = hv;
                else if (gc < 2 * H)
                    *reinterpret_cast<__half2*>(&g_gd[(size_t)grow * H + (gc - H)]) = hv;
                else
                    *reinterpret_cast<__half2*>(&g_hs[(size_t)grow * 2 * H + H + (gc - 2 * H)]) = hv;
            }
        }
    }
}

// ---------------------------------------------------------------------------
// Kernel 3: per-edge. 16 lanes/edge (2 edges/warp) + L2 prefetch of the next
//           iteration's feature rows (no extra register pressure).
// ---------------------------------------------------------------------------
__device__ __forceinline__ float fast_tanh(float v) {
    float r;
    asm("tanh.approx.f32 %0, %1;" : "=f"(r) : "f"(v));
    return r;
}
__device__ __forceinline__ void st_cs_v2(float* p, float a, float b) {
    asm volatile("st.global.cs.v2.f32 [%0], {%1,%2};" :: "l"(p), "f"(a), "f"(b));
}
__device__ __forceinline__ void prefetch_l2(const void* p) {
    asm volatile("prefetch.global.L2 [%0];" :: "l"(p));
}

__global__ __launch_bounds__(256) void edge_kernel(const int* __restrict__ src,
                                                   const int* __restrict__ dst,
                                                   const float* __restrict__ dvec,
                                                   const float* __restrict__ Wclf,
                                                   float* __restrict__ a_out) {
    const float inv = rsqrtf(2.0f * H);   // 1/sqrt(192)
    const int lane = threadIdx.x & 31;
    const int sub  = lane >> 4;           // which edge of the pair
    const int sl   = lane & 15;           // sublane within edge, owns elems 6sl..6sl+5
    const int warp = (blockIdx.x * blockDim.x + threadIdx.x) >> 5;
    const int nwarps = (gridDim.x * blockDim.x) >> 5;
    const int NPAIRS = N_EDGES / 2;

    float c0[6], c1[6];
    #pragma unroll
    for (int q = 0; q < 6; ++q) {
        c0[q] = Wclf[6 * sl + q];
        c1[q] = Wclf[H + 6 * sl + q];
    }

    for (int p = warp; p < NPAIRS; p += nwarps) {
        int e = 2 * p + sub;
        int s = __ldg(src + e), t = __ldg(dst + e);
        float ed = __ldg(dvec + s) * __ldg(dvec + t);

        // Prefetch next iteration's feature rows into L2 (lanes 0-4 of each
        // half-warp cover the 3 lines of hs[s'] and 2 lines of gd[t']).
        int pn = p + nwarps;
        if (pn < NPAIRS) {
            int en = 2 * pn + sub;
            int sn = __ldg(src + en), tn = __ldg(dst + en);
            if (sl < 3)
                prefetch_l2((const char*)(g_hs + (size_t)sn * 2 * H) + (sl << 7));
            else if (sl < 5)
                prefetch_l2((const char*)(g_gd + (size_t)tn * H) + ((sl - 3) << 7));
        }

        const __half2* fh = reinterpret_cast<const __half2*>(g_hs + (size_t)s * 2 * H) + 3 * sl;
        const __half2* fg = reinterpret_cast<const __half2*>(g_hs + (size_t)s * 2 * H + H) + 3 * sl;
        const __half2* fd = reinterpret_cast<const __half2*>(g_gd + (size_t)t * H) + 3 * sl;

        float s0 = 0.f, s1 = 0.f;
        float av[6];
        #pragma unroll
        for (int q = 0; q < 3; ++q) {
            float2 gd = __half22float2(__ldg(fd + q));
            float2 gs = __half22float2(__ldg(fg + q));
            float2 hh = __half22float2(__ldg(fh + q));
            float a0 = fast_tanh((gd.x + gs.x) * inv);
            float a1 = fast_tanh((gd.y + gs.y) * inv);
            av[2 * q]     = a0;
            av[2 * q + 1] = a1;
            float m0 = hh.x * a0 * ed;
            float m1 = hh.y * a1 * ed;
            s0 = fmaf(c0[2 * q], m0, fmaf(c0[2 * q + 1], m1, s0));
            s1 = fmaf(c1[2 * q], m0, fmaf(c1[2 * q + 1], m1, s1));
        }
        float* aop = a_out + (size_t)e * H + 6 * sl;
        st_cs_v2(aop + 0, av[0], av[1]);
        st_cs_v2(aop + 2, av[2], av[3]);
        st_cs_v2(aop + 4, av[4], av[5]);

        #pragma unroll
        for (int off = 8; off > 0; off >>= 1) {
            s0 += __shfl_down_sync(0xffffffffu, s0, off);
            s1 += __shfl_down_sync(0xffffffffu, s1, off);
        }
        if (sl == 0) {
            atomicAdd(&g_zacc[2 * t + 0], s0);
            atomicAdd(&g_zacc[2 * t + 1], s1);
        }
    }
}

// ---------------------------------------------------------------------------
// Kernel 4: z = log_softmax(zacc + b_clf) over the 2 classes.
// ---------------------------------------------------------------------------
__global__ void final_kernel(const float* __restrict__ b_clf, float* __restrict__ z_out) {
    int n = blockIdx.x * blockDim.x + threadIdx.x;
    if (n >= N_NODES) return;
    float l0 = g_zacc[2 * n + 0] + b_clf[0];
    float l1 = g_zacc[2 * n + 1] + b_clf[1];
    float m = fmaxf(l0, l1);
    float lse = m + logf(expf(l0 - m) + expf(l1 - m));
    z_out[2 * n + 0] = l0 - lse;
    z_out[2 * n + 1] = l1 - lse;
}

// ---------------------------------------------------------------------------
extern "C" void kernel_launch(void* const* d_in, const int* in_sizes, int n_in,
                              void* d_out, int out_size) {
    const float* x      = (const float*)d_in[0];
    const float* dvec   = (const float*)d_in[1];
    const int*   src    = (const int*)  d_in[2];
    const int*   dst    = (const int*)  d_in[3];
    const float* W_in   = (const float*)d_in[4];
    const float* b_in   = (const float*)d_in[5];
    const float* W_gate = (const float*)d_in[6];
    const float* b_gate = (const float*)d_in[7];
    const float* W_clf  = (const float*)d_in[8];
    const float* b_clf  = (const float*)d_in[9];

    float* out   = (float*)d_out;
    float* z_out = out;                 // [N, 2]
    float* a_out = out + 2 * N_NODES;   // [E, 96]

    prep_kernel<<<F, 256>>>(W_in, b_in, W_gate, b_gate);

    dim3 ggrid((N_NODES + BM - 1) / BM, F / BN);
    gemm_tc_kernel<<<ggrid, 256>>>(x);

    edge_kernel<<<2048, 256>>>(src, dst, dvec, W_clf, a_out);

    final_kernel<<<(N_NODES + 255) / 256, 256>>>(b_clf, z_out);
}

// round 13
// speedup vs baseline: 1.8742x; 1.8742x over previous
#include <cuda_runtime.h>
#include <cuda_fp16.h>
#include <math.h>

#define N_NODES 50000
#define N_EDGES 800000
#define H       96
#define IN_DIM  256
#define F       288   // combined output: [ h(96) | g_d(96) | g_s(96) ]

// Scratch (device globals — no allocation in kernel_launch)
__device__ __half g_hs[(size_t)N_NODES * 2 * H];   // [h*d_src(96) | g_s(96)] per node
__device__ __half g_gd[(size_t)N_NODES * H];       // g_d per node
__device__ float  g_WcT[IN_DIM * F];               // combined weight, tf32-pre-rounded
__device__ float  g_bc[F];
__device__ float  g_zacc[2 * N_NODES];

__device__ __forceinline__ unsigned f2tf32(float f) {
    unsigned u;
    asm("cvt.rna.tf32.f32 %0, %1;" : "=r"(u) : "f"(f));
    return u;
}

// ---------------------------------------------------------------------------
// Kernel 1: build combined weight WcT[k][r] (tf32-rounded) and bias; zero zacc.
// ---------------------------------------------------------------------------
__global__ void prep_kernel(const float* __restrict__ W_in, const float* __restrict__ b_in,
                            const float* __restrict__ W_gate, const float* __restrict__ b_gate) {
    int r = blockIdx.x;      // 0..287
    int k = threadIdx.x;     // 0..255
    float v;
    if (r < H) {
        v = W_in[r * IN_DIM + k];
    } else if (r < 2 * H) {
        int i = r - H;
        float acc = 0.f;
        #pragma unroll 4
        for (int j = 0; j < H; ++j) acc = fmaf(W_gate[i * (2 * H) + j], W_in[j * IN_DIM + k], acc);
        v = acc;
    } else {
        int i = r - 2 * H;
        float acc = 0.f;
        #pragma unroll 4
        for (int j = 0; j < H; ++j) acc = fmaf(W_gate[i * (2 * H) + H + j], W_in[j * IN_DIM + k], acc);
        v = acc;
    }
    g_WcT[k * F + r] = __uint_as_float(f2tf32(v));

    if (k == 0) {
        float b;
        if (r < H) {
            b = b_in[r];
        } else if (r < 2 * H) {
            int i = r - H;
            float acc = 0.f;
            for (int j = 0; j < H; ++j) acc = fmaf(W_gate[i * (2 * H) + j], b_in[j], acc);
            b = acc;
        } else {
            int i = r - 2 * H;
            float acc = 0.f;
            for (int j = 0; j < H; ++j) acc = fmaf(W_gate[i * (2 * H) + H + j], b_in[j], acc);
            b = acc + b_gate[i];
        }
        g_bc[r] = b;
    }

    for (int idx = blockIdx.x * blockDim.x + threadIdx.x; idx < 2 * N_NODES;
         idx += gridDim.x * blockDim.x)
        g_zacc[idx] = 0.f;
}

// ---------------------------------------------------------------------------
// Kernel 2: feat = x @ WcT + bc via tf32 mma, cp.async double-buffered.
//   Epilogue -> fp16: g_hs = [h*d | g_s], g_gd = g_d.
// ---------------------------------------------------------------------------
#define BM 128
#define BN 96
#define BK 32
#define AS_LD 36
#define BS_LD 104
#define KTILES (IN_DIM / BK)   // 8

__device__ __forceinline__ unsigned smem_u32(const void* p) {
    return (unsigned)__cvta_generic_to_shared(p);
}
__device__ __forceinline__ void cp_async16(unsigned dst, const void* src, bool valid) {
    int sz = valid ? 16 : 0;
    asm volatile("cp.async.cg.shared.global [%0], [%1], 16, %2;\n"
                 :: "r"(dst), "l"(src), "r"(sz));
}

__global__ __launch_bounds__(256) void gemm_tc_kernel(const float* __restrict__ x,
                                                      const float* __restrict__ dvec) {
    __shared__ float As[2][BM][AS_LD];
    __shared__ float Bs[2][BK][BS_LD];

    const int tid  = threadIdx.x;
    const int warp = tid >> 5;
    const int lane = tid & 31;
    const int gid  = lane >> 2;
    const int tig  = lane & 3;

    const int row0 = blockIdx.x * BM;
    const int col0 = blockIdx.y * BN;
    const int wm = warp >> 1;
    const int wn = warp & 1;
    const int m_warp = wm * 32;
    const int n_warp = wn * 48;

    float c[2][6][4];
    #pragma unroll
    for (int i = 0; i < 2; ++i)
        #pragma unroll
        for (int j = 0; j < 6; ++j)
            #pragma unroll
            for (int q = 0; q < 4; ++q) c[i][j][q] = 0.f;

    const int ar = tid >> 3;
    const int ac = (tid & 7) * 4;
    const int bk = tid >> 3;
    const int bc = (tid & 7) * 12;

    auto issue_tile = [&](int buf, int t) {
        int k0 = t * BK;
        #pragma unroll
        for (int p = 0; p < 4; ++p) {
            int r = ar + p * 32;
            int grow = row0 + r;
            bool valid = (grow < N_NODES);
            const float* srcp = x + (size_t)(valid ? grow : 0) * IN_DIM + k0 + ac;
            cp_async16(smem_u32(&As[buf][r][ac]), srcp, valid);
        }
        const float* bp = g_WcT + (size_t)(k0 + bk) * F + col0 + bc;
        #pragma unroll
        for (int q = 0; q < 3; ++q)
            cp_async16(smem_u32(&Bs[buf][bk][bc + q * 4]), bp + q * 4, true);
        asm volatile("cp.async.commit_group;\n");
    };

    issue_tile(0, 0);

    for (int t = 0; t < KTILES; ++t) {
        int cur = t & 1;
        if (t + 1 < KTILES) {
            issue_tile(cur ^ 1, t + 1);
            asm volatile("cp.async.wait_group 1;\n");
        } else {
            asm volatile("cp.async.wait_group 0;\n");
        }
        __syncthreads();

        #pragma unroll
        for (int ks = 0; ks < 4; ++ks) {
            const int kk = ks * 8;
            unsigned a[2][4], b[6][2];
            #pragma unroll
            for (int mt = 0; mt < 2; ++mt) {
                int rA = m_warp + mt * 16 + gid;
                a[mt][0] = f2tf32(As[cur][rA    ][kk + tig    ]);
                a[mt][1] = f2tf32(As[cur][rA + 8][kk + tig    ]);
                a[mt][2] = f2tf32(As[cur][rA    ][kk + tig + 4]);
                a[mt][3] = f2tf32(As[cur][rA + 8][kk + tig + 4]);
            }
            #pragma unroll
            for (int nt = 0; nt < 6; ++nt) {
                int cB = n_warp + nt * 8 + gid;
                b[nt][0] = __float_as_uint(Bs[cur][kk + tig    ][cB]);
                b[nt][1] = __float_as_uint(Bs[cur][kk + tig + 4][cB]);
            }
            #pragma unroll
            for (int mt = 0; mt < 2; ++mt)
                #pragma unroll
                for (int nt = 0; nt < 6; ++nt) {
                    asm volatile(
                        "mma.sync.aligned.m16n8k8.row.col.f32.tf32.tf32.f32 "
                        "{%0,%1,%2,%3}, {%4,%5,%6,%7}, {%8,%9}, {%0,%1,%2,%3};\n"
                        : "+f"(c[mt][nt][0]), "+f"(c[mt][nt][1]),
                          "+f"(c[mt][nt][2]), "+f"(c[mt][nt][3])
                        : "r"(a[mt][0]), "r"(a[mt][1]), "r"(a[mt][2]), "r"(a[mt][3]),
                          "r"(b[nt][0]), "r"(b[nt][1]));
                }
        }
        __syncthreads();
    }

    // epilogue: add bias, convert fp16; h block pre-scaled by d[node].
    #pragma unroll
    for (int mt = 0; mt < 2; ++mt) {
        #pragma unroll
        for (int hf = 0; hf < 2; ++hf) {
            int grow = row0 + m_warp + mt * 16 + gid + hf * 8;
            if (grow >= N_NODES) continue;
            float dsc = (col0 == 0) ? __ldg(dvec + grow) : 1.0f;
            #pragma unroll
            for (int nt = 0; nt < 6; ++nt) {
                int gc = col0 + n_warp + nt * 8 + 2 * tig;
                float v0 = c[mt][nt][hf * 2 + 0] + g_bc[gc];
                float v1 = c[mt][nt][hf * 2 + 1] + g_bc[gc + 1];
                if (gc < H) {             // h * d[src]
                    __half2 hv = __floats2half2_rn(v0 * dsc, v1 * dsc);
                    *reinterpret_cast<__half2*>(&g_hs[(size_t)grow * 2 * H + gc]) = hv;
                } else if (gc < 2 * H) {  // g_d
                    __half2 hv = __floats2half2_rn(v0, v1);
                    *reinterpret_cast<__half2*>(&g_gd[(size_t)grow * H + (gc - H)]) = hv;
                } else {                  // g_s
                    __half2 hv = __floats2half2_rn(v0, v1);
                    *reinterpret_cast<__half2*>(&g_hs[(size_t)grow * 2 * H + H + (gc - 2 * H)]) = hv;
                }
            }
        }
    }
}

// ---------------------------------------------------------------------------
// Kernel 3: per-edge. 16 lanes per edge (2 edges per warp), half2 gathers,
//           vectorized streaming stores. (R4 structure — do not perturb.)
// ---------------------------------------------------------------------------
__device__ __forceinline__ float fast_tanh(float v) {
    float r;
    asm("tanh.approx.f32 %0, %1;" : "=f"(r) : "f"(v));
    return r;
}
__device__ __forceinline__ void st_cs_v2(float* p, float a, float b) {
    asm volatile("st.global.cs.v2.f32 [%0], {%1,%2};" :: "l"(p), "f"(a), "f"(b));
}

__global__ __launch_bounds__(256) void edge_kernel(const int* __restrict__ src,
                                                   const int* __restrict__ dst,
                                                   const float* __restrict__ dvec,
                                                   const float* __restrict__ Wclf,
                                                   float* __restrict__ a_out) {
    const float inv = rsqrtf(2.0f * H);   // 1/sqrt(192)
    const int lane = threadIdx.x & 31;
    const int sub  = lane >> 4;           // which edge of the pair
    const int sl   = lane & 15;           // sublane within edge, owns elems 6sl..6sl+5
    const int warp = (blockIdx.x * blockDim.x + threadIdx.x) >> 5;
    const int nwarps = (gridDim.x * blockDim.x) >> 5;
    const int NPAIRS = N_EDGES / 2;

    float c0[6], c1[6];
    #pragma unroll
    for (int q = 0; q < 6; ++q) {
        c0[q] = Wclf[6 * sl + q];
        c1[q] = Wclf[H + 6 * sl + q];
    }

    for (int p = warp; p < NPAIRS; p += nwarps) {
        int e = 2 * p + sub;
        int s = __ldg(src + e), t = __ldg(dst + e);
        float ddst = (sl == 0) ? __ldg(dvec + t) : 0.f;   // only the reducing lane needs it

        const __half2* fh = reinterpret_cast<const __half2*>(g_hs + (size_t)s * 2 * H) + 3 * sl;
        const __half2* fg = reinterpret_cast<const __half2*>(g_hs + (size_t)s * 2 * H + H) + 3 * sl;
        const __half2* fd = reinterpret_cast<const __half2*>(g_gd + (size_t)t * H) + 3 * sl;

        float s0 = 0.f, s1 = 0.f;
        float av[6];
        #pragma unroll
        for (int q = 0; q < 3; ++q) {
            float2 gd = __half22float2(__ldg(fd + q));
            float2 gs = __half22float2(__ldg(fg + q));
            float2 hh = __half22float2(__ldg(fh + q));
            float a0 = fast_tanh((gd.x + gs.x) * inv);
            float a1 = fast_tanh((gd.y + gs.y) * inv);
            av[2 * q]     = a0;
            av[2 * q + 1] = a1;
            float m0 = hh.x * a0;   // h already scaled by d[src]
            float m1 = hh.y * a1;
            s0 = fmaf(c0[2 * q], m0, fmaf(c0[2 * q + 1], m1, s0));
            s1 = fmaf(c1[2 * q], m0, fmaf(c1[2 * q + 1], m1, s1));
        }
        float* aop = a_out + (size_t)e * H + 6 * sl;
        st_cs_v2(aop + 0, av[0], av[1]);
        st_cs_v2(aop + 2, av[2], av[3]);
        st_cs_v2(aop + 4, av[4], av[5]);

        #pragma unroll
        for (int off = 8; off > 0; off >>= 1) {
            s0 += __shfl_down_sync(0xffffffffu, s0, off);
            s1 += __shfl_down_sync(0xffffffffu, s1, off);
        }
        if (sl == 0) {
            atomicAdd(&g_zacc[2 * t + 0], s0 * ddst);
            atomicAdd(&g_zacc[2 * t + 1], s1 * ddst);
        }
    }
}

// ---------------------------------------------------------------------------
// Kernel 4: z = log_softmax(zacc + b_clf) over the 2 classes.
// ---------------------------------------------------------------------------
__global__ void final_kernel(const float* __restrict__ b_clf, float* __restrict__ z_out) {
    int n = blockIdx.x * blockDim.x + threadIdx.x;
    if (n >= N_NODES) return;
    float l0 = g_zacc[2 * n + 0] + b_clf[0];
    float l1 = g_zacc[2 * n + 1] + b_clf[1];
    float m = fmaxf(l0, l1);
    float lse = m + logf(expf(l0 - m) + expf(l1 - m));
    z_out[2 * n + 0] = l0 - lse;
    z_out[2 * n + 1] = l1 - lse;
}

// ---------------------------------------------------------------------------
extern "C" void kernel_launch(void* const* d_in, const int* in_sizes, int n_in,
                              void* d_out, int out_size) {
    const float* x      = (const float*)d_in[0];
    const float* dvec   = (const float*)d_in[1];
    const int*   src    = (const int*)  d_in[2];
    const int*   dst    = (const int*)  d_in[3];
    const float* W_in   = (const float*)d_in[4];
    const float* b_in   = (const float*)d_in[5];
    const float* W_gate = (const float*)d_in[6];
    const float* b_gate = (const float*)d_in[7];
    const float* W_clf  = (const float*)d_in[8];
    const float* b_clf  = (const float*)d_in[9];

    float* out   = (float*)d_out;
    float* z_out = out;                 // [N, 2]
    float* a_out = out + 2 * N_NODES;   // [E, 96]

    prep_kernel<<<F, 256>>>(W_in, b_in, W_gate, b_gate);

    dim3 ggrid((N_NODES + BM - 1) / BM, F / BN);
    gemm_tc_kernel<<<ggrid, 256>>>(x, dvec);

    edge_kernel<<<2048, 256>>>(src, dst, dvec, W_clf, a_out);

    final_kernel<<<(N_NODES + 255) / 256, 256>>>(b_clf, z_out);
}

// round 15
// speedup vs baseline: 1.8772x; 1.0016x over previous
#include <cuda_runtime.h>
#include <cuda_fp16.h>
#include <math.h>

#define N_NODES 50000
#define N_EDGES 800000
#define H       96
#define IN_DIM  256
#define F       288   // combined output: [ h(96) | g_d(96) | g_s(96) ]

// Scratch (device globals — no allocation in kernel_launch)
__device__ __half g_hs[(size_t)N_NODES * 2 * H];   // [h*d_src(96) | g_s(96)] per node
__device__ __half g_gd[(size_t)N_NODES * H];       // g_d per node
__device__ float  g_WcT[IN_DIM * F];               // combined weight, tf32-pre-rounded
__device__ float  g_bc[F];
__device__ float  g_zacc[2 * N_NODES];

__device__ __forceinline__ unsigned f2tf32(float f) {
    unsigned u;
    asm("cvt.rna.tf32.f32 %0, %1;" : "=r"(u) : "f"(f));
    return u;
}

// ---------------------------------------------------------------------------
// Kernel 1: build combined weight WcT[k][r] (tf32-rounded) and bias; zero zacc.
// ---------------------------------------------------------------------------
__global__ void prep_kernel(const float* __restrict__ W_in, const float* __restrict__ b_in,
                            const float* __restrict__ W_gate, const float* __restrict__ b_gate) {
    int r = blockIdx.x;      // 0..287
    int k = threadIdx.x;     // 0..255
    float v;
    if (r < H) {
        v = W_in[r * IN_DIM + k];
    } else if (r < 2 * H) {
        int i = r - H;
        float acc = 0.f;
        #pragma unroll 4
        for (int j = 0; j < H; ++j) acc = fmaf(W_gate[i * (2 * H) + j], W_in[j * IN_DIM + k], acc);
        v = acc;
    } else {
        int i = r - 2 * H;
        float acc = 0.f;
        #pragma unroll 4
        for (int j = 0; j < H; ++j) acc = fmaf(W_gate[i * (2 * H) + H + j], W_in[j * IN_DIM + k], acc);
        v = acc;
    }
    g_WcT[k * F + r] = __uint_as_float(f2tf32(v));

    if (k == 0) {
        float b;
        if (r < H) {
            b = b_in[r];
        } else if (r < 2 * H) {
            int i = r - H;
            float acc = 0.f;
            for (int j = 0; j < H; ++j) acc = fmaf(W_gate[i * (2 * H) + j], b_in[j], acc);
            b = acc;
        } else {
            int i = r - 2 * H;
            float acc = 0.f;
            for (int j = 0; j < H; ++j) acc = fmaf(W_gate[i * (2 * H) + H + j], b_in[j], acc);
            b = acc + b_gate[i];
        }
        g_bc[r] = b;
    }

    for (int idx = blockIdx.x * blockDim.x + threadIdx.x; idx < 2 * N_NODES;
         idx += gridDim.x * blockDim.x)
        g_zacc[idx] = 0.f;
}

// ---------------------------------------------------------------------------
// Kernel 2: feat = x @ WcT + bc via tf32 mma, cp.async 3-stage pipeline,
//   one __syncthreads per k-tile. Epilogue -> fp16: g_hs=[h*d|g_s], g_gd=g_d.
// ---------------------------------------------------------------------------
#define BM 128
#define BN 96
#define BK 32
#define AS_LD 36
#define BS_LD 104
#define KTILES (IN_DIM / BK)   // 8
#define STAGES 3

__device__ __forceinline__ unsigned smem_u32(const void* p) {
    return (unsigned)__cvta_generic_to_shared(p);
}
__device__ __forceinline__ void cp_async16(unsigned dst, const void* src, bool valid) {
    int sz = valid ? 16 : 0;
    asm volatile("cp.async.cg.shared.global [%0], [%1], 16, %2;\n"
                 :: "r"(dst), "l"(src), "r"(sz));
}

__global__ __launch_bounds__(256) void gemm_tc_kernel(const float* __restrict__ x,
                                                      const float* __restrict__ dvec) {
    __shared__ float As[STAGES][BM][AS_LD];
    __shared__ float Bs[STAGES][BK][BS_LD];

    const int tid  = threadIdx.x;
    const int warp = tid >> 5;
    const int lane = tid & 31;
    const int gid  = lane >> 2;
    const int tig  = lane & 3;

    const int row0 = blockIdx.x * BM;
    const int col0 = blockIdx.y * BN;
    const int wm = warp >> 1;
    const int wn = warp & 1;
    const int m_warp = wm * 32;
    const int n_warp = wn * 48;

    float c[2][6][4];
    #pragma unroll
    for (int i = 0; i < 2; ++i)
        #pragma unroll
        for (int j = 0; j < 6; ++j)
            #pragma unroll
            for (int q = 0; q < 4; ++q) c[i][j][q] = 0.f;

    const int ar = tid >> 3;
    const int ac = (tid & 7) * 4;
    const int bk = tid >> 3;
    const int bc = (tid & 7) * 12;

    auto issue_tile = [&](int buf, int t) {
        int k0 = t * BK;
        #pragma unroll
        for (int p = 0; p < 4; ++p) {
            int r = ar + p * 32;
            int grow = row0 + r;
            bool valid = (grow < N_NODES);
            const float* srcp = x + (size_t)(valid ? grow : 0) * IN_DIM + k0 + ac;
            cp_async16(smem_u32(&As[buf][r][ac]), srcp, valid);
        }
        const float* bp = g_WcT + (size_t)(k0 + bk) * F + col0 + bc;
        #pragma unroll
        for (int q = 0; q < 3; ++q)
            cp_async16(smem_u32(&Bs[buf][bk][bc + q * 4]), bp + q * 4, true);
        asm volatile("cp.async.commit_group;\n");
    };

    issue_tile(0, 0);
    issue_tile(1, 1);

    for (int t = 0; t < KTILES; ++t) {
        int cur = t % STAGES;
        if (t < KTILES - 1) {
            asm volatile("cp.async.wait_group 1;\n");   // tile t complete (t+1 may fly)
        } else {
            asm volatile("cp.async.wait_group 0;\n");
        }
        __syncthreads();   // all warps see tile t data; all done reading buf (t-1)%3

        if (t + 2 < KTILES)
            issue_tile((t + 2) % STAGES, t + 2);        // overwrites buf read at iter t-1

        #pragma unroll
        for (int ks = 0; ks < 4; ++ks) {
            const int kk = ks * 8;
            unsigned a[2][4], b[6][2];
            #pragma unroll
            for (int mt = 0; mt < 2; ++mt) {
                int rA = m_warp + mt * 16 + gid;
                a[mt][0] = f2tf32(As[cur][rA    ][kk + tig    ]);
                a[mt][1] = f2tf32(As[cur][rA + 8][kk + tig    ]);
                a[mt][2] = f2tf32(As[cur][rA    ][kk + tig + 4]);
                a[mt][3] = f2tf32(As[cur][rA + 8][kk + tig + 4]);
            }
            #pragma unroll
            for (int nt = 0; nt < 6; ++nt) {
                int cB = n_warp + nt * 8 + gid;
                b[nt][0] = __float_as_uint(Bs[cur][kk + tig    ][cB]);
                b[nt][1] = __float_as_uint(Bs[cur][kk + tig + 4][cB]);
            }
            #pragma unroll
            for (int mt = 0; mt < 2; ++mt)
                #pragma unroll
                for (int nt = 0; nt < 6; ++nt) {
                    asm volatile(
                        "mma.sync.aligned.m16n8k8.row.col.f32.tf32.tf32.f32 "
                        "{%0,%1,%2,%3}, {%4,%5,%6,%7}, {%8,%9}, {%0,%1,%2,%3};\n"
                        : "+f"(c[mt][nt][0]), "+f"(c[mt][nt][1]),
                          "+f"(c[mt][nt][2]), "+f"(c[mt][nt][3])
                        : "r"(a[mt][0]), "r"(a[mt][1]), "r"(a[mt][2]), "r"(a[mt][3]),
                          "r"(b[nt][0]), "r"(b[nt][1]));
                }
        }
    }

    // epilogue: add bias, convert fp16; h block pre-scaled by d[node].
    #pragma unroll
    for (int mt = 0; mt < 2; ++mt) {
        #pragma unroll
        for (int hf = 0; hf < 2; ++hf) {
            int grow = row0 + m_warp + mt * 16 + gid + hf * 8;
            if (grow >= N_NODES) continue;
            float dsc = (col0 == 0) ? __ldg(dvec + grow) : 1.0f;
            #pragma unroll
            for (int nt = 0; nt < 6; ++nt) {
                int gc = col0 + n_warp + nt * 8 + 2 * tig;
                float v0 = c[mt][nt][hf * 2 + 0] + g_bc[gc];
                float v1 = c[mt][nt][hf * 2 + 1] + g_bc[gc + 1];
                if (gc < H) {             // h * d[src]
                    __half2 hv = __floats2half2_rn(v0 * dsc, v1 * dsc);
                    *reinterpret_cast<__half2*>(&g_hs[(size_t)grow * 2 * H + gc]) = hv;
                } else if (gc < 2 * H) {  // g_d
                    __half2 hv = __floats2half2_rn(v0, v1);
                    *reinterpret_cast<__half2*>(&g_gd[(size_t)grow * H + (gc - H)]) = hv;
                } else {                  // g_s
                    __half2 hv = __floats2half2_rn(v0, v1);
                    *reinterpret_cast<__half2*>(&g_hs[(size_t)grow * 2 * H + H + (gc - 2 * H)]) = hv;
                }
            }
        }
    }
}

// ---------------------------------------------------------------------------
// Kernel 3: per-edge. 16 lanes per edge (2 edges per warp), half2 gathers,
//           vectorized streaming stores. (R4 structure — frozen.)
// ---------------------------------------------------------------------------
__device__ __forceinline__ float fast_tanh(float v) {
    float r;
    asm("tanh.approx.f32 %0, %1;" : "=f"(r) : "f"(v));
    return r;
}
__device__ __forceinline__ void st_cs_v2(float* p, float a, float b) {
    asm volatile("st.global.cs.v2.f32 [%0], {%1,%2};" :: "l"(p), "f"(a), "f"(b));
}

__global__ __launch_bounds__(256) void edge_kernel(const int* __restrict__ src,
                                                   const int* __restrict__ dst,
                                                   const float* __restrict__ dvec,
                                                   const float* __restrict__ Wclf,
                                                   float* __restrict__ a_out) {
    const float inv = rsqrtf(2.0f * H);   // 1/sqrt(192)
    const int lane = threadIdx.x & 31;
    const int sub  = lane >> 4;           // which edge of the pair
    const int sl   = lane & 15;           // sublane within edge, owns elems 6sl..6sl+5
    const int warp = (blockIdx.x * blockDim.x + threadIdx.x) >> 5;
    const int nwarps = (gridDim.x * blockDim.x) >> 5;
    const int NPAIRS = N_EDGES / 2;

    float c0[6], c1[6];
    #pragma unroll
    for (int q = 0; q < 6; ++q) {
        c0[q] = Wclf[6 * sl + q];
        c1[q] = Wclf[H + 6 * sl + q];
    }

    for (int p = warp; p < NPAIRS; p += nwarps) {
        int e = 2 * p + sub;
        int s = __ldg(src + e), t = __ldg(dst + e);
        float ddst = (sl == 0) ? __ldg(dvec + t) : 0.f;

        const __half2* fh = reinterpret_cast<const __half2*>(g_hs + (size_t)s * 2 * H) + 3 * sl;
        const __half2* fg = reinterpret_cast<const __half2*>(g_hs + (size_t)s * 2 * H + H) + 3 * sl;
        const __half2* fd = reinterpret_cast<const __half2*>(g_gd + (size_t)t * H) + 3 * sl;

        float s0 = 0.f, s1 = 0.f;
        float av[6];
        #pragma unroll
        for (int q = 0; q < 3; ++q) {
            float2 gd = __half22float2(__ldg(fd + q));
            float2 gs = __half22float2(__ldg(fg + q));
            float2 hh = __half22float2(__ldg(fh + q));
            float a0 = fast_tanh((gd.x + gs.x) * inv);
            float a1 = fast_tanh((gd.y + gs.y) * inv);
            av[2 * q]     = a0;
            av[2 * q + 1] = a1;
            float m0 = hh.x * a0;   // h already scaled by d[src]
            float m1 = hh.y * a1;
            s0 = fmaf(c0[2 * q], m0, fmaf(c0[2 * q + 1], m1, s0));
            s1 = fmaf(c1[2 * q], m0, fmaf(c1[2 * q + 1], m1, s1));
        }
        float* aop = a_out + (size_t)e * H + 6 * sl;
        st_cs_v2(aop + 0, av[0], av[1]);
        st_cs_v2(aop + 2, av[2], av[3]);
        st_cs_v2(aop + 4, av[4], av[5]);

        #pragma unroll
        for (int off = 8; off > 0; off >>= 1) {
            s0 += __shfl_down_sync(0xffffffffu, s0, off);
            s1 += __shfl_down_sync(0xffffffffu, s1, off);
        }
        if (sl == 0) {
            atomicAdd(&g_zacc[2 * t + 0], s0 * ddst);
            atomicAdd(&g_zacc[2 * t + 1], s1 * ddst);
        }
    }
}

// ---------------------------------------------------------------------------
// Kernel 4: z = log_softmax(zacc + b_clf) over the 2 classes.
// ---------------------------------------------------------------------------
__global__ void final_kernel(const float* __restrict__ b_clf, float* __restrict__ z_out) {
    int n = blockIdx.x * blockDim.x + threadIdx.x;
    if (n >= N_NODES) return;
    float l0 = g_zacc[2 * n + 0] + b_clf[0];
    float l1 = g_zacc[2 * n + 1] + b_clf[1];
    float m = fmaxf(l0, l1);
    float lse = m + logf(expf(l0 - m) + expf(l1 - m));
    z_out[2 * n + 0] = l0 - lse;
    z_out[2 * n + 1] = l1 - lse;
}

// ---------------------------------------------------------------------------
extern "C" void kernel_launch(void* const* d_in, const int* in_sizes, int n_in,
                              void* d_out, int out_size) {
    const float* x      = (const float*)d_in[0];
    const float* dvec   = (const float*)d_in[1];
    const int*   src    = (const int*)  d_in[2];
    const int*   dst    = (const int*)  d_in[3];
    const float* W_in   = (const float*)d_in[4];
    const float* b_in   = (const float*)d_in[5];
    const float* W_gate = (const float*)d_in[6];
    const float* b_gate = (const float*)d_in[7];
    const float* W_clf  = (const float*)d_in[8];
    const float* b_clf  = (const float*)d_in[9];

    float* out   = (float*)d_out;
    float* z_out = out;                 // [N, 2]
    float* a_out = out + 2 * N_NODES;   // [E, 96]

    prep_kernel<<<F, 256>>>(W_in, b_in, W_gate, b_gate);

    dim3 ggrid((N_NODES + BM - 1) / BM, F / BN);
    gemm_tc_kernel<<<ggrid, 256>>>(x, dvec);

    edge_kernel<<<2048, 256>>>(src, dst, dvec, W_clf, a_out);

    final_kernel<<<(N_NODES + 255) / 256, 256>>>(b_clf, z_out);
}